// round 1
// baseline (speedup 1.0000x reference)
#include <cuda_runtime.h>
#include <math.h>

// Problem shape (fixed by reference setup_inputs)
#define BATCH 16
#define SEQ   2048
#define DIM   512

// Tiling
#define THREADS 256
#define NWARP   8
#define TQ      16     // query rows per block
#define RPW     2      // query rows per warp (TQ / NWARP)
#define TK      16     // key rows staged in smem per tile
#define DPL     16     // DIM / 32 lanes
#define NCHUNK  4      // DPL / 4 (float4 chunks per lane)

// Scratch: normalized x and per-row L2 norms (device globals, no allocation)
__device__ float g_xn [BATCH * SEQ * DIM];
__device__ float g_nrm[BATCH * SEQ];

// ---------------------------------------------------------------------------
// Kernel 1: per-row L2 norm; write xn = x / ||x|| and ||x||.
// One warp per row. Lane owns d = {c*128 + lane*4 .. +3}, c in [0,4).
// ---------------------------------------------------------------------------
__global__ void prep_kernel(const float* __restrict__ x) {
    int warp = threadIdx.x >> 5;
    int lane = threadIdx.x & 31;
    size_t row = (size_t)blockIdx.x * NWARP + warp;
    const float* xr = x + row * DIM;

    float v[DPL];
    float ss = 0.f;
#pragma unroll
    for (int c = 0; c < NCHUNK; c++) {
        float4 t = *(const float4*)(xr + c * 128 + lane * 4);
        v[c*4+0] = t.x; v[c*4+1] = t.y; v[c*4+2] = t.z; v[c*4+3] = t.w;
        ss += t.x*t.x + t.y*t.y + t.z*t.z + t.w*t.w;
    }
#pragma unroll
    for (int off = 16; off; off >>= 1)
        ss += __shfl_xor_sync(0xffffffffu, ss, off);

    float rinv = rsqrtf(ss);
    float nrm  = ss * rinv;     // == sqrt(ss)

    float* xo = g_xn + row * DIM;
#pragma unroll
    for (int c = 0; c < NCHUNK; c++) {
        float4 t;
        t.x = v[c*4+0] * rinv;
        t.y = v[c*4+1] * rinv;
        t.z = v[c*4+2] * rinv;
        t.w = v[c*4+3] * rinv;
        *(float4*)(xo + c * 128 + lane * 4) = t;
    }
    if (lane == 0) g_nrm[row] = nrm;
}

// ---------------------------------------------------------------------------
// Kernel 2: flash-style cosine attention.
//   scores(i,j) = xn_i . xn_j   (bounded [-1,1] -> no max tracking needed)
//   out_i = sum_j exp(s_ij) * ||x_j|| * xn_j  /  sum_j exp(s_ij)
// Block: one batch, TQ=16 query rows. Warp: 2 query rows, acc in registers.
// K tile (TK=16 rows of xn + norms) staged in static smem.
// ---------------------------------------------------------------------------
__global__ void __launch_bounds__(THREADS)
attn_kernel(float* __restrict__ out) {
    __shared__ float sk[TK * DIM];
    __shared__ float sn[TK];

    int b    = blockIdx.y;
    int warp = threadIdx.x >> 5;
    int lane = threadIdx.x & 31;

    const float* xb = g_xn  + (size_t)b * SEQ * DIM;
    const float* nb = g_nrm + (size_t)b * SEQ;

    int q0 = blockIdx.x * TQ + warp * RPW;

    float q[RPW][DPL];
    float acc[RPW][DPL];
    float lsum[RPW];

#pragma unroll
    for (int r = 0; r < RPW; r++) {
        lsum[r] = 0.f;
        const float* qr = xb + (size_t)(q0 + r) * DIM;
#pragma unroll
        for (int c = 0; c < NCHUNK; c++) {
            float4 t = *(const float4*)(qr + c * 128 + lane * 4);
            q[r][c*4+0] = t.x; q[r][c*4+1] = t.y;
            q[r][c*4+2] = t.z; q[r][c*4+3] = t.w;
            acc[r][c*4+0] = 0.f; acc[r][c*4+1] = 0.f;
            acc[r][c*4+2] = 0.f; acc[r][c*4+3] = 0.f;
        }
    }

    for (int t0 = 0; t0 < SEQ; t0 += TK) {
        __syncthreads();
        // Stage TK key rows (normalized) + norms. 8 float4 per thread.
        const float4* src = (const float4*)(xb + (size_t)t0 * DIM);
        float4* dst = (float4*)sk;
#pragma unroll
        for (int i = 0; i < (TK * DIM / 4) / THREADS; i++)
            dst[threadIdx.x + i * THREADS] = src[threadIdx.x + i * THREADS];
        if (threadIdx.x < TK) sn[threadIdx.x] = nb[t0 + threadIdx.x];
        __syncthreads();

#pragma unroll 1
        for (int j = 0; j < TK; j++) {
            float k[DPL];
#pragma unroll
            for (int c = 0; c < NCHUNK; c++) {
                float4 t = *(const float4*)(sk + j * DIM + c * 128 + lane * 4);
                k[c*4+0] = t.x; k[c*4+1] = t.y; k[c*4+2] = t.z; k[c*4+3] = t.w;
            }
            float s0 = 0.f, s1 = 0.f;
#pragma unroll
            for (int d = 0; d < DPL; d++) {
                s0 += q[0][d] * k[d];
                s1 += q[1][d] * k[d];
            }
#pragma unroll
            for (int off = 16; off; off >>= 1) {
                s0 += __shfl_xor_sync(0xffffffffu, s0, off);
                s1 += __shfl_xor_sync(0xffffffffu, s1, off);
            }
            float nj = sn[j];
            float p0 = __expf(s0);
            float p1 = __expf(s1);
            lsum[0] += p0;
            lsum[1] += p1;
            float w0 = p0 * nj;
            float w1 = p1 * nj;
#pragma unroll
            for (int d = 0; d < DPL; d++) {
                acc[0][d] += w0 * k[d];
                acc[1][d] += w1 * k[d];
            }
        }
    }

#pragma unroll
    for (int r = 0; r < RPW; r++) {
        float inv = 1.0f / lsum[r];
        float* dstp = out + ((size_t)b * SEQ + q0 + r) * DIM;
#pragma unroll
        for (int c = 0; c < NCHUNK; c++) {
            float4 t;
            t.x = acc[r][c*4+0] * inv;
            t.y = acc[r][c*4+1] * inv;
            t.z = acc[r][c*4+2] * inv;
            t.w = acc[r][c*4+3] * inv;
            *(float4*)(dstp + c * 128 + lane * 4) = t;
        }
    }
}

// ---------------------------------------------------------------------------
extern "C" void kernel_launch(void* const* d_in, const int* in_sizes, int n_in,
                              void* d_out, int out_size) {
    const float* x = (const float*)d_in[0];
    float* out = (float*)d_out;

    // Kernel 1: normalize rows (B*N rows, 8 warps/block)
    prep_kernel<<<(BATCH * SEQ) / NWARP, THREADS>>>(x);

    // Kernel 2: attention
    dim3 grid(SEQ / TQ, BATCH);
    attn_kernel<<<grid, THREADS>>>(out);
}

// round 10
// speedup vs baseline: 9.9126x; 9.9126x over previous
#include <cuda_runtime.h>
#include <cuda_fp16.h>
#include <stdint.h>

#define BATCH 16
#define SEQ   2048
#define DIM   512

// GEMM tiling: CTA 128x128, K-stage 32 fp16 (=64B rows, SW64), 3-stage pipeline,
// STATIC shared memory (48KB) and all scratch referenced from DEVICE code only
// (passing __device__ globals as host-side kernel args silently binds the host
// shadow symbol, which GB300's ATS happily dereferences as zeros).
#define TM 128
#define TN 128
#define KSTEP 32
#define NSTAGE 3
#define ATILE (TM * 64)                 /* 8192 B */
#define BTILE (TN * 64)                 /* 8192 B */
#define STAGE_BYTES (ATILE + BTILE)     /* 16384 B */
#define GT 256

// Device scratch (allocation-free)
__device__ __align__(1024) __half g_xn[BATCH * SEQ * DIM]; // normalized x, fp16
__device__ __align__(1024) __half g_xt[BATCH * SEQ * DIM]; // x^T per batch [D][N], fp16
__device__ __align__(1024) float  g_S [(size_t)BATCH * SEQ * SEQ]; // scores fp32
__device__ __align__(1024) __half g_p [(size_t)BATCH * SEQ * SEQ]; // softmax probs fp16

// ---------------------------------------------------------------------------
__device__ __forceinline__ uint32_t smem_u32(const void* p) {
    uint32_t a;
    asm("{ .reg .u64 t; cvta.to.shared.u64 t, %1; cvt.u32.u64 %0, t; }" : "=r"(a) : "l"(p));
    return a;
}
// SW64 swizzle for 64B rows: XOR chunk index (bits[4:5]) with row bits[7:8].
__device__ __forceinline__ uint32_t swz64(uint32_t off) {
    return off ^ ((off >> 3) & 0x30u);
}
__device__ __forceinline__ void cp16(uint32_t saddr, const void* g) {
    asm volatile("cp.async.cg.shared.global [%0], [%1], 16;" :: "r"(saddr), "l"(g) : "memory");
}
__device__ __forceinline__ void cp_commit() {
    asm volatile("cp.async.commit_group;" ::: "memory");
}
template <int N> __device__ __forceinline__ void cp_wait() {
    asm volatile("cp.async.wait_group %0;" :: "n"(N) : "memory");
}
__device__ __forceinline__ void ldsm4(uint32_t& r0, uint32_t& r1, uint32_t& r2, uint32_t& r3,
                                      uint32_t addr) {
    asm volatile("ldmatrix.sync.aligned.m8n8.x4.shared.b16 {%0,%1,%2,%3}, [%4];"
                 : "=r"(r0), "=r"(r1), "=r"(r2), "=r"(r3) : "r"(addr));
}
__device__ __forceinline__ void mma16816(float* d, const uint32_t* a, const uint32_t* b) {
    asm volatile(
        "mma.sync.aligned.m16n8k16.row.col.f32.f16.f16.f32 "
        "{%0,%1,%2,%3}, {%4,%5,%6,%7}, {%8,%9}, {%0,%1,%2,%3};"
        : "+f"(d[0]), "+f"(d[1]), "+f"(d[2]), "+f"(d[3])
        : "r"(a[0]), "r"(a[1]), "r"(a[2]), "r"(a[3]), "r"(b[0]), "r"(b[1]));
}

// ---------------------------------------------------------------------------
// Kernel 1: row L2-normalize, write fp16 to g_xn. One warp per row.
// ---------------------------------------------------------------------------
__global__ void __launch_bounds__(256) prep_kernel(const float* __restrict__ x) {
    int warp = threadIdx.x >> 5, lane = threadIdx.x & 31;
    size_t row = (size_t)blockIdx.x * 8 + warp;
    const float* xr = x + row * DIM;

    float v[16];
    float ss = 0.f;
#pragma unroll
    for (int c = 0; c < 4; c++) {
        float4 t = *(const float4*)(xr + c * 128 + lane * 4);
        v[c*4+0] = t.x; v[c*4+1] = t.y; v[c*4+2] = t.z; v[c*4+3] = t.w;
        ss += t.x*t.x + t.y*t.y + t.z*t.z + t.w*t.w;
    }
#pragma unroll
    for (int off = 16; off; off >>= 1) ss += __shfl_xor_sync(0xffffffffu, ss, off);
    float rinv = rsqrtf(ss);

#pragma unroll
    for (int c = 0; c < 4; c++) {
        __half2 h0 = __floats2half2_rn(v[c*4+0]*rinv, v[c*4+1]*rinv);
        __half2 h1 = __floats2half2_rn(v[c*4+2]*rinv, v[c*4+3]*rinv);
        size_t o = row * DIM + c * 128 + lane * 4;
        *(__half2*)(g_xn + o)     = h0;
        *(__half2*)(g_xn + o + 2) = h1;
    }
}

// ---------------------------------------------------------------------------
// Kernel 2: transpose x (per batch [N,D] -> [D,N]) into g_xt, fp16.
// ---------------------------------------------------------------------------
__global__ void __launch_bounds__(256) transpose_kernel(const float* __restrict__ x) {
    __shared__ float tile[32][33];
    int b = blockIdx.z;
    int n0 = blockIdx.x * 32, d0 = blockIdx.y * 32;
    int tx = threadIdx.x, ty = threadIdx.y;

    const float* xb = x + ((size_t)b * SEQ + n0) * DIM + d0;
#pragma unroll
    for (int k = 0; k < 4; k++)
        tile[ty + 8*k][tx] = xb[(size_t)(ty + 8*k) * DIM + tx];
    __syncthreads();
#pragma unroll
    for (int k = 0; k < 4; k++) {
        size_t o = ((size_t)b * DIM + d0 + ty + 8*k) * SEQ + n0 + tx;
        g_xt[o] = __float2half(tile[tx][ty + 8*k]);
    }
}

// ---------------------------------------------------------------------------
// GEMM: C[m,n] = sum_k A[m,k]*B[n,k]; fp16 K-major inputs, fp32 out.
// MODE 0: A=B=g_xn (K=DIM), C=g_S.   MODE 1: A=g_p, B=g_xt (K=SEQ), C=param.
// Scratch pointers are resolved in DEVICE code (correct device addresses).
// ---------------------------------------------------------------------------
template <int MODE>
__global__ void __launch_bounds__(GT)
gemm_kernel(float* __restrict__ Cparam) {
    constexpr int KTOT   = (MODE == 0) ? DIM : SEQ;
    const size_t aStride = (MODE == 0) ? (size_t)SEQ * DIM : (size_t)SEQ * SEQ;
    const size_t bStride = (MODE == 0) ? (size_t)SEQ * DIM : (size_t)DIM * SEQ;
    const size_t cStride = (MODE == 0) ? (size_t)SEQ * SEQ : (size_t)SEQ * DIM;
    const int    cCols   = (MODE == 0) ? SEQ : DIM;
    const __half* A = (MODE == 0) ? g_xn : g_p;
    const __half* B = (MODE == 0) ? g_xn : g_xt;
    float* C        = (MODE == 0) ? g_S  : Cparam;

    __shared__ __align__(1024) char smem[NSTAGE * STAGE_BYTES];  // 49152 B
    const uint32_t sb = smem_u32(smem);
    const int tid = threadIdx.x, lane = tid & 31, wid = tid >> 5;
    const int wm = wid >> 2, wn = wid & 3;
    const int b = blockIdx.z;
    const int m0 = blockIdx.x * TM, n0 = blockIdx.y * TN;

    const __half* pa = A + (size_t)b * aStride + (size_t)m0 * KTOT;
    const __half* pb = B + (size_t)b * bStride + (size_t)n0 * KTOT;

    auto load_stage = [&](int s) {
        const uint32_t base = sb + (uint32_t)(s % NSTAGE) * STAGE_BYTES;
        const int k0 = s * KSTEP;
#pragma unroll
        for (int i = 0; i < 2; i++) {       // A: 128 rows x 4 16B chunks
            int idx = tid + i * GT;
            int r = idx >> 2, c = idx & 3;
            cp16(base + swz64((uint32_t)(r * 64 + c * 16)),
                 pa + (size_t)r * KTOT + k0 + c * 8);
        }
#pragma unroll
        for (int i = 0; i < 2; i++) {       // B: 128 rows x 4 16B chunks
            int idx = tid + i * GT;
            int r = idx >> 2, c = idx & 3;
            cp16(base + ATILE + swz64((uint32_t)(r * 64 + c * 16)),
                 pb + (size_t)r * KTOT + k0 + c * 8);
        }
        cp_commit();
    };

    float acc[4][4][4];
#pragma unroll
    for (int im = 0; im < 4; im++)
#pragma unroll
        for (int in = 0; in < 4; in++)
#pragma unroll
            for (int j = 0; j < 4; j++) acc[im][in][j] = 0.f;

    constexpr int S = KTOT / KSTEP;
    load_stage(0); load_stage(1);

    for (int i = 0; i < S; i++) {
        if (S - 1 - i >= 1) cp_wait<1>();
        else                cp_wait<0>();
        __syncthreads();
        if (i + 2 < S) load_stage(i + 2);  // slot (i+2)%3 == (i-1)%3, already consumed

        const uint32_t abase = sb + (uint32_t)(i % NSTAGE) * STAGE_BYTES;
        const uint32_t bbase = abase + ATILE;
#pragma unroll
        for (int ks = 0; ks < 2; ks++) {   // 2 x K=16 per stage
            uint32_t af[4][4];
            uint32_t bf[4][2];
#pragma unroll
            for (int im = 0; im < 4; im++) {
                int row = wm * 64 + im * 16 + (lane & 15);
                uint32_t off = (uint32_t)(row * 64 + ks * 32 + ((lane >> 4) & 1) * 16);
                ldsm4(af[im][0], af[im][1], af[im][2], af[im][3], abase + swz64(off));
            }
#pragma unroll
            for (int jn = 0; jn < 2; jn++) {
                int row = wn * 32 + jn * 16 + (lane & 7) + ((lane >> 4) & 1) * 8;
                uint32_t off = (uint32_t)(row * 64 + ks * 32 + ((lane >> 3) & 1) * 16);
                uint32_t r0, r1, r2, r3;
                ldsm4(r0, r1, r2, r3, bbase + swz64(off));
                bf[jn*2+0][0] = r0; bf[jn*2+0][1] = r1;
                bf[jn*2+1][0] = r2; bf[jn*2+1][1] = r3;
            }
#pragma unroll
            for (int im = 0; im < 4; im++)
#pragma unroll
                for (int in = 0; in < 4; in++)
                    mma16816(acc[im][in], af[im], bf[in]);
        }
    }

    float* cb = C + (size_t)b * cStride;
#pragma unroll
    for (int im = 0; im < 4; im++) {
        int r0 = m0 + wm * 64 + im * 16 + (lane >> 2);
#pragma unroll
        for (int in = 0; in < 4; in++) {
            int col = n0 + wn * 32 + in * 8 + (lane & 3) * 2;
            *(float2*)&cb[(size_t)r0       * cCols + col] = make_float2(acc[im][in][0], acc[im][in][1]);
            *(float2*)&cb[(size_t)(r0 + 8) * cCols + col] = make_float2(acc[im][in][2], acc[im][in][3]);
        }
    }
}

// ---------------------------------------------------------------------------
// Softmax over rows of g_S (scores in [-1,1] -> no max pass), p -> g_p fp16.
// ---------------------------------------------------------------------------
__global__ void __launch_bounds__(256) softmax_kernel() {
    __shared__ float wsum[8];
    int tid = threadIdx.x;
    size_t off = ((size_t)blockIdx.y * SEQ + blockIdx.x) * SEQ;

    float e[8];
    float s = 0.f;
    const float* src = g_S + off + tid * 8;
#pragma unroll
    for (int i = 0; i < 2; i++) {
        float4 t = *(const float4*)(src + i * 4);
        e[i*4+0] = __expf(t.x); e[i*4+1] = __expf(t.y);
        e[i*4+2] = __expf(t.z); e[i*4+3] = __expf(t.w);
        s += e[i*4+0] + e[i*4+1] + e[i*4+2] + e[i*4+3];
    }
#pragma unroll
    for (int o = 16; o; o >>= 1) s += __shfl_xor_sync(0xffffffffu, s, o);
    if ((tid & 31) == 0) wsum[tid >> 5] = s;
    __syncthreads();
    float tot = 0.f;
#pragma unroll
    for (int w = 0; w < 8; w++) tot += wsum[w];
    float inv = 1.0f / tot;

    __half h[8];
#pragma unroll
    for (int j = 0; j < 8; j++) h[j] = __float2half(e[j] * inv);
    *(uint4*)(g_p + off + tid * 8) = *(uint4*)h;
}

// ---------------------------------------------------------------------------
extern "C" void kernel_launch(void* const* d_in, const int* in_sizes, int n_in,
                              void* d_out, int out_size) {
    const float* x = (const float*)d_in[0];   // genuine device pointer
    float* out = (float*)d_out;               // genuine device pointer

    // 1) normalize rows -> g_xn (fp16)
    prep_kernel<<<BATCH * SEQ / 8, 256>>>(x);
    // 2) transpose -> g_xt (fp16, K-major for GEMM2 B)
    transpose_kernel<<<dim3(SEQ/32, DIM/32, BATCH), dim3(32, 8)>>>(x);
    // 3) g_S = XN . XN^T   (M=N=2048, K=512)
    gemm_kernel<0><<<dim3(SEQ/TM, SEQ/TN, BATCH), GT>>>(nullptr);
    // 4) g_p = softmax(g_S) (fp16)
    softmax_kernel<<<dim3(SEQ, BATCH), 256>>>();
    // 5) out = P . X   (M=2048, N=512, K=2048)
    gemm_kernel<1><<<dim3(SEQ/TM, DIM/TN, BATCH), GT>>>(out);
}

// round 17
// speedup vs baseline: 11.3396x; 1.1440x over previous
#include <cuda_runtime.h>
#include <cuda_fp16.h>
#include <stdint.h>

#define BATCH 16
#define SEQ   2048
#define DIM   512

#define TM 128
#define TN 128
#define KSTEP 32
#define NSTAGE 3
#define ATILE (TM * 64)                 /* 8192 B */
#define BTILE (TN * 64)                 /* 8192 B */
#define STAGE_BYTES (ATILE + BTILE)     /* 16384 B */
#define GT 256

// Device scratch (allocation-free). All referenced from DEVICE code only —
// host-side references to __device__ globals bind the host shadow symbol,
// which GB300's ATS dereferences silently as zeros.
__device__ __align__(1024) __half g_xn[BATCH * SEQ * DIM];          // normalized x, fp16
__device__ __align__(1024) __half g_xt[BATCH * SEQ * DIM];          // x^T per batch [D][N], fp16
__device__ __align__(1024) __half g_p [(size_t)BATCH * SEQ * SEQ];  // E = exp(S), fp16
__device__ __align__(1024) float  g_rsum[BATCH * SEQ];              // row sums of E

// ---------------------------------------------------------------------------
__device__ __forceinline__ uint32_t smem_u32(const void* p) {
    uint32_t a;
    asm("{ .reg .u64 t; cvta.to.shared.u64 t, %1; cvt.u32.u64 %0, t; }" : "=r"(a) : "l"(p));
    return a;
}
// SW64 swizzle for 64B rows: XOR chunk index (bits[4:5]) with row bits[7:8].
__device__ __forceinline__ uint32_t swz64(uint32_t off) {
    return off ^ ((off >> 3) & 0x30u);
}
__device__ __forceinline__ void cp16(uint32_t saddr, const void* g) {
    asm volatile("cp.async.cg.shared.global [%0], [%1], 16;" :: "r"(saddr), "l"(g) : "memory");
}
__device__ __forceinline__ void cp_commit() {
    asm volatile("cp.async.commit_group;" ::: "memory");
}
template <int N> __device__ __forceinline__ void cp_wait() {
    asm volatile("cp.async.wait_group %0;" :: "n"(N) : "memory");
}
__device__ __forceinline__ void ldsm4(uint32_t& r0, uint32_t& r1, uint32_t& r2, uint32_t& r3,
                                      uint32_t addr) {
    asm volatile("ldmatrix.sync.aligned.m8n8.x4.shared.b16 {%0,%1,%2,%3}, [%4];"
                 : "=r"(r0), "=r"(r1), "=r"(r2), "=r"(r3) : "r"(addr));
}
__device__ __forceinline__ void mma16816(float* d, const uint32_t* a, const uint32_t* b) {
    asm volatile(
        "mma.sync.aligned.m16n8k16.row.col.f32.f16.f16.f32 "
        "{%0,%1,%2,%3}, {%4,%5,%6,%7}, {%8,%9}, {%0,%1,%2,%3};"
        : "+f"(d[0]), "+f"(d[1]), "+f"(d[2]), "+f"(d[3])
        : "r"(a[0]), "r"(a[1]), "r"(a[2]), "r"(a[3]), "r"(b[0]), "r"(b[1]));
}

// ---------------------------------------------------------------------------
// Kernel 1: row L2-normalize -> g_xn fp16. One warp per row.
// Also zeroes g_rsum[row] (graph replay would otherwise accumulate).
// ---------------------------------------------------------------------------
__global__ void __launch_bounds__(256) prep_kernel(const float* __restrict__ x) {
    int warp = threadIdx.x >> 5, lane = threadIdx.x & 31;
    size_t row = (size_t)blockIdx.x * 8 + warp;
    const float* xr = x + row * DIM;

    if (lane == 0) g_rsum[row] = 0.f;

    float v[16];
    float ss = 0.f;
#pragma unroll
    for (int c = 0; c < 4; c++) {
        float4 t = *(const float4*)(xr + c * 128 + lane * 4);
        v[c*4+0] = t.x; v[c*4+1] = t.y; v[c*4+2] = t.z; v[c*4+3] = t.w;
        ss += t.x*t.x + t.y*t.y + t.z*t.z + t.w*t.w;
    }
#pragma unroll
    for (int off = 16; off; off >>= 1) ss += __shfl_xor_sync(0xffffffffu, ss, off);
    float rinv = rsqrtf(ss);

#pragma unroll
    for (int c = 0; c < 4; c++) {
        __half2 h0 = __floats2half2_rn(v[c*4+0]*rinv, v[c*4+1]*rinv);
        __half2 h1 = __floats2half2_rn(v[c*4+2]*rinv, v[c*4+3]*rinv);
        size_t o = row * DIM + c * 128 + lane * 4;
        *(__half2*)(g_xn + o)     = h0;
        *(__half2*)(g_xn + o + 2) = h1;
    }
}

// ---------------------------------------------------------------------------
// Kernel 2: transpose x (per batch [N,D] -> [D,N]) into g_xt, fp16.
// ---------------------------------------------------------------------------
__global__ void __launch_bounds__(256) transpose_kernel(const float* __restrict__ x) {
    __shared__ float tile[32][33];
    int b = blockIdx.z;
    int n0 = blockIdx.x * 32, d0 = blockIdx.y * 32;
    int tx = threadIdx.x, ty = threadIdx.y;

    const float* xb = x + ((size_t)b * SEQ + n0) * DIM + d0;
#pragma unroll
    for (int k = 0; k < 4; k++)
        tile[ty + 8*k][tx] = xb[(size_t)(ty + 8*k) * DIM + tx];
    __syncthreads();
#pragma unroll
    for (int k = 0; k < 4; k++) {
        size_t o = ((size_t)b * DIM + d0 + ty + 8*k) * SEQ + n0 + tx;
        g_xt[o] = __float2half(tile[tx][ty + 8*k]);
    }
}

// ---------------------------------------------------------------------------
// GEMM: C[m,n] = sum_k A[m,k]*B[n,k]; fp16 K-major inputs, fp32 accum.
// MODE 0: A=B=g_xn (K=DIM); epilogue: E=exp(acc) -> g_p fp16, rowsum atomics.
// MODE 1: A=g_p, B=g_xt (K=SEQ); epilogue: scale by 1/g_rsum -> Cparam fp32.
// ---------------------------------------------------------------------------
template <int MODE>
__global__ void __launch_bounds__(GT)
gemm_kernel(float* __restrict__ Cparam) {
    constexpr int KTOT   = (MODE == 0) ? DIM : SEQ;
    const size_t aStride = (MODE == 0) ? (size_t)SEQ * DIM : (size_t)SEQ * SEQ;
    const size_t bStride = (MODE == 0) ? (size_t)SEQ * DIM : (size_t)DIM * SEQ;
    const __half* A = (MODE == 0) ? g_xn : g_p;
    const __half* B = (MODE == 0) ? g_xn : g_xt;

    __shared__ __align__(1024) char smem[NSTAGE * STAGE_BYTES];  // 49152 B
    const uint32_t sb = smem_u32(smem);
    const int tid = threadIdx.x, lane = tid & 31, wid = tid >> 5;
    const int wm = wid >> 2, wn = wid & 3;
    const int b = blockIdx.z;
    const int m0 = blockIdx.x * TM, n0 = blockIdx.y * TN;

    const __half* pa = A + (size_t)b * aStride + (size_t)m0 * KTOT;
    const __half* pb = B + (size_t)b * bStride + (size_t)n0 * KTOT;

    auto load_stage = [&](int s) {
        const uint32_t base = sb + (uint32_t)(s % NSTAGE) * STAGE_BYTES;
        const int k0 = s * KSTEP;
#pragma unroll
        for (int i = 0; i < 2; i++) {       // A: 128 rows x 4 16B chunks
            int idx = tid + i * GT;
            int r = idx >> 2, c = idx & 3;
            cp16(base + swz64((uint32_t)(r * 64 + c * 16)),
                 pa + (size_t)r * KTOT + k0 + c * 8);
        }
#pragma unroll
        for (int i = 0; i < 2; i++) {       // B: 128 rows x 4 16B chunks
            int idx = tid + i * GT;
            int r = idx >> 2, c = idx & 3;
            cp16(base + ATILE + swz64((uint32_t)(r * 64 + c * 16)),
                 pb + (size_t)r * KTOT + k0 + c * 8);
        }
        cp_commit();
    };

    float acc[4][4][4];
#pragma unroll
    for (int im = 0; im < 4; im++)
#pragma unroll
        for (int in = 0; in < 4; in++)
#pragma unroll
            for (int j = 0; j < 4; j++) acc[im][in][j] = 0.f;

    constexpr int S = KTOT / KSTEP;
    load_stage(0); load_stage(1);

    for (int i = 0; i < S; i++) {
        if (S - 1 - i >= 1) cp_wait<1>();
        else                cp_wait<0>();
        __syncthreads();
        if (i + 2 < S) load_stage(i + 2);

        const uint32_t abase = sb + (uint32_t)(i % NSTAGE) * STAGE_BYTES;
        const uint32_t bbase = abase + ATILE;
#pragma unroll
        for (int ks = 0; ks < 2; ks++) {
            uint32_t af[4][4];
            uint32_t bf[4][2];
#pragma unroll
            for (int im = 0; im < 4; im++) {
                int row = wm * 64 + im * 16 + (lane & 15);
                uint32_t off = (uint32_t)(row * 64 + ks * 32 + ((lane >> 4) & 1) * 16);
                ldsm4(af[im][0], af[im][1], af[im][2], af[im][3], abase + swz64(off));
            }
#pragma unroll
            for (int jn = 0; jn < 2; jn++) {
                int row = wn * 32 + jn * 16 + (lane & 7) + ((lane >> 4) & 1) * 8;
                uint32_t off = (uint32_t)(row * 64 + ks * 32 + ((lane >> 3) & 1) * 16);
                uint32_t r0, r1, r2, r3;
                ldsm4(r0, r1, r2, r3, bbase + swz64(off));
                bf[jn*2+0][0] = r0; bf[jn*2+0][1] = r1;
                bf[jn*2+1][0] = r2; bf[jn*2+1][1] = r3;
            }
#pragma unroll
            for (int im = 0; im < 4; im++)
#pragma unroll
                for (int in = 0; in < 4; in++)
                    mma16816(acc[im][in], af[im], bf[in]);
        }
    }

    if (MODE == 0) {
        // Epilogue: E = exp(S) -> g_p fp16; per-row partial sums -> g_rsum atomics.
        __half* eb = g_p + (size_t)b * SEQ * SEQ;
#pragma unroll
        for (int im = 0; im < 4; im++) {
            int r0 = m0 + wm * 64 + im * 16 + (lane >> 2);
            float s0 = 0.f, s1 = 0.f;
#pragma unroll
            for (int in = 0; in < 4; in++) {
                int col = n0 + wn * 32 + in * 8 + (lane & 3) * 2;
                float e0 = __expf(acc[im][in][0]);
                float e1 = __expf(acc[im][in][1]);
                float e2 = __expf(acc[im][in][2]);
                float e3 = __expf(acc[im][in][3]);
                s0 += e0 + e1;
                s1 += e2 + e3;
                *(__half2*)&eb[(size_t)r0       * SEQ + col] = __floats2half2_rn(e0, e1);
                *(__half2*)&eb[(size_t)(r0 + 8) * SEQ + col] = __floats2half2_rn(e2, e3);
            }
            // reduce over the 4 lanes sharing each row (lane&3 varies)
            s0 += __shfl_xor_sync(0xffffffffu, s0, 1);
            s0 += __shfl_xor_sync(0xffffffffu, s0, 2);
            s1 += __shfl_xor_sync(0xffffffffu, s1, 1);
            s1 += __shfl_xor_sync(0xffffffffu, s1, 2);
            if ((lane & 3) == 0) {
                atomicAdd(&g_rsum[b * SEQ + r0],     s0);
                atomicAdd(&g_rsum[b * SEQ + r0 + 8], s1);
            }
        }
    } else {
        // Epilogue: out = acc / rowsum
        float* cb = Cparam + (size_t)b * SEQ * DIM;
#pragma unroll
        for (int im = 0; im < 4; im++) {
            int r0 = m0 + wm * 64 + im * 16 + (lane >> 2);
            float inv0 = 1.0f / g_rsum[b * SEQ + r0];
            float inv1 = 1.0f / g_rsum[b * SEQ + r0 + 8];
#pragma unroll
            for (int in = 0; in < 4; in++) {
                int col = n0 + wn * 32 + in * 8 + (lane & 3) * 2;
                *(float2*)&cb[(size_t)r0       * DIM + col] =
                    make_float2(acc[im][in][0] * inv0, acc[im][in][1] * inv0);
                *(float2*)&cb[(size_t)(r0 + 8) * DIM + col] =
                    make_float2(acc[im][in][2] * inv1, acc[im][in][3] * inv1);
            }
        }
    }
}

// ---------------------------------------------------------------------------
extern "C" void kernel_launch(void* const* d_in, const int* in_sizes, int n_in,
                              void* d_out, int out_size) {
    const float* x = (const float*)d_in[0];
    float* out = (float*)d_out;

    // 1) normalize rows -> g_xn; zero g_rsum
    prep_kernel<<<BATCH * SEQ / 8, 256>>>(x);
    // 2) transpose -> g_xt (K-major B for GEMM2)
    transpose_kernel<<<dim3(SEQ/32, DIM/32, BATCH), dim3(32, 8)>>>(x);
    // 3) g_p = exp(XN . XN^T), g_rsum = row sums   (M=N=2048, K=512)
    gemm_kernel<0><<<dim3(SEQ/TM, SEQ/TN, BATCH), GT>>>(nullptr);
    // 4) out = (E . X) / rowsum   (M=2048, N=512, K=2048)
    gemm_kernel<1><<<dim3(SEQ/TM, DIM/TN, BATCH), GT>>>(out);
}